// round 4
// baseline (speedup 1.0000x reference)
#include <cuda_runtime.h>
#include <cuda_bf16.h>

// Haar 3D wavelet (2x2x2, stride 2, causal temporal replicate-pad).
// x: (2,3,33,512,512) fp32 -> out: (2,24,17,256,256) fp32
// Channel layout: out[b, f*3 + c, t, h, w], f bits = (t_flip<<2)|(h_flip<<1)|w_flip.
// R4: R3 (2 cols/thread, 4x LDG.128 __ldcg, 8x STG.64 __stcs) with 1024-thread
// blocks (fewer CTAs, same occupancy at 32 regs).

#define HAAR_SCALE 0.3536f

#define IN_T   33
#define IN_H   512
#define IN_W   512
#define OUT_T  17
#define OUT_H  256
#define OUT_W  256
#define NBC    6            // b*c = 2*3
#define WP     128          // output-column pairs per row (256/2)
#define TPB    1024

__global__ __launch_bounds__(TPB)
void haar3d_kernel(const float* __restrict__ x, float* __restrict__ out)
{
    const int idx = blockIdx.x * TPB + threadIdx.x;
    // idx -> (bc, t, h, wp); wp fastest for coalescing
    const int wp   = idx & (WP - 1);           // 0..127
    const int h    = (idx >> 7) & (OUT_H - 1); // 0..255
    const int rest = idx >> 15;                // t + OUT_T*bc
    const int t    = rest % OUT_T;
    const int bc   = rest / OUT_T;
    if (bc >= NBC) return;

    const size_t IN_FRAME = (size_t)IN_H * IN_W;      // 262144
    const int t1 = 2 * t;                             // current frame
    const int t0 = (t1 - 1 < 0) ? 0 : (t1 - 1);       // causal replicate pad
    const int hh = 2 * h;
    const size_t col = (size_t)wp * 4;                // 4 input floats = 2 out cols

    const float* bx = x + (size_t)bc * IN_T * IN_FRAME;
    const float4 r00 = __ldcg((const float4*)(bx + (size_t)t0 * IN_FRAME + (size_t)(hh    ) * IN_W + col));
    const float4 r01 = __ldcg((const float4*)(bx + (size_t)t0 * IN_FRAME + (size_t)(hh + 1) * IN_W + col));
    const float4 r10 = __ldcg((const float4*)(bx + (size_t)t1 * IN_FRAME + (size_t)(hh    ) * IN_W + col));
    const float4 r11 = __ldcg((const float4*)(bx + (size_t)t1 * IN_FRAME + (size_t)(hh + 1) * IN_W + col));

    float2 o[8];

    #pragma unroll
    for (int k = 0; k < 2; k++) {
        // k=0 -> (.x,.y) pair, k=1 -> (.z,.w) pair
        const float v000 = k ? r00.z : r00.x;  // t-,h0,w0
        const float v001 = k ? r00.w : r00.y;  // t-,h0,w1
        const float v010 = k ? r01.z : r01.x;  // t-,h1,w0
        const float v011 = k ? r01.w : r01.y;  // t-,h1,w1
        const float v100 = k ? r10.z : r10.x;  // t ,h0,w0
        const float v101 = k ? r10.w : r10.y;
        const float v110 = k ? r11.z : r11.x;
        const float v111 = k ? r11.w : r11.y;

        // stage 1: along w
        const float a0 = v000 + v001, a1 = v000 - v001;
        const float a2 = v010 + v011, a3 = v010 - v011;
        const float a4 = v100 + v101, a5 = v100 - v101;
        const float a6 = v110 + v111, a7 = v110 - v111;
        // stage 2: along h
        const float b0 = a0 + a2, b1 = a1 + a3, b2 = a0 - a2, b3 = a1 - a3;
        const float b4 = a4 + a6, b5 = a5 + a7, b6 = a4 - a6, b7 = a5 - a7;
        // stage 3: along t; filter f bits = (t_flip<<2)|(h_flip<<1)|w_flip
        float r[8];
        r[0] = (b0 + b4) * HAAR_SCALE;  // 000
        r[1] = (b1 + b5) * HAAR_SCALE;  // 001 w
        r[2] = (b2 + b6) * HAAR_SCALE;  // 010 h
        r[3] = (b3 + b7) * HAAR_SCALE;  // 011 hw
        r[4] = (b0 - b4) * HAAR_SCALE;  // 100 t
        r[5] = (b1 - b5) * HAAR_SCALE;  // 101 tw
        r[6] = (b2 - b6) * HAAR_SCALE;  // 110 th
        r[7] = (b3 - b7) * HAAR_SCALE;  // 111 thw
        #pragma unroll
        for (int f = 0; f < 8; f++) {
            if (k == 0) o[f].x = r[f]; else o[f].y = r[f];
        }
    }

    const int  b  = bc / 3;
    const int  c  = bc - 3 * b;
    const size_t OUT_FRAME = (size_t)OUT_H * OUT_W;   // 65536
    const size_t spatial = (size_t)t * OUT_FRAME + (size_t)h * OUT_W + (size_t)wp * 2;

    #pragma unroll
    for (int f = 0; f < 8; f++) {
        const size_t ch = (size_t)(b * 24 + f * 3 + c);
        __stcs((float2*)(out + ch * OUT_T * OUT_FRAME + spatial), o[f]);
    }
}

extern "C" void kernel_launch(void* const* d_in, const int* in_sizes, int n_in,
                              void* d_out, int out_size)
{
    const float* x = (const float*)d_in[0];
    float* out = (float*)d_out;
    // total threads = NBC * OUT_T * OUT_H * WP = 6*17*256*128 = 3,342,336
    const int total = NBC * OUT_T * OUT_H * WP;
    const int blocks = (total + TPB - 1) / TPB;
    haar3d_kernel<<<blocks, TPB>>>(x, out);
}